// round 2
// baseline (speedup 1.0000x reference)
#include <cuda_runtime.h>
#include <cstdint>

#define E_NUM   500000
#define N_NUM   100000
#define H_DIM   256
#define PAIRS   (E_NUM / 2)          // 250000 (E is even)
#define BN_EPS  1e-5f
#define NBLK1   ((PAIRS + 255) / 256)  // 977

typedef unsigned long long u64;

// -------- device scratch (no allocation allowed) --------
__device__ float g_sum[H_DIM];
__device__ float g_sumsq[H_DIM];
__device__ u64   g_nc2[PAIRS * 8];      // packed nc pairs, 16 MB
__device__ float g_P1[H_DIM * 8];       // Wo@Wp
__device__ float g_P2[H_DIM * 8];       // Wv@P1
__device__ float g_Craw[H_DIM * 8];     // W2@P2 (unscaled)
__device__ u64   g_dhdup[8];            // 0.5*d duplicated
__device__ u64   g_w1dup[H_DIM * 8];    // W1^T duplicated (j,d)
__device__ u64   g_b1dup[H_DIM];
__device__ u64   g_mdup[H_DIM * 8];     // 0.5*a[j]*Craw[j,k] duplicated

// -------- f32x2 helpers --------
__device__ __forceinline__ u64 pack2(float lo, float hi) {
    u64 r;
    asm("mov.b64 %0, {%1, %2};" : "=l"(r)
        : "r"(__float_as_uint(lo)), "r"(__float_as_uint(hi)));
    return r;
}
__device__ __forceinline__ void unpack2(u64 v, float &lo, float &hi) {
    unsigned int a, b;
    asm("mov.b64 {%0, %1}, %2;" : "=r"(a), "=r"(b) : "l"(v));
    lo = __uint_as_float(a); hi = __uint_as_float(b);
}
__device__ __forceinline__ u64 fma2(u64 a, u64 b, u64 c) {
    u64 d;
    asm("fma.rn.f32x2 %0, %1, %2, %3;" : "=l"(d) : "l"(a), "l"(b), "l"(c));
    return d;
}
__device__ __forceinline__ u64 add2(u64 a, u64 b) {
    u64 d;
    asm("add.rn.f32x2 %0, %1, %2;" : "=l"(d) : "l"(a), "l"(b));
    return d;
}
__device__ __forceinline__ u64 relu2(u64 h) {
    float lo, hi; unpack2(h, lo, hi);
    return pack2(fmaxf(lo, 0.f), fmaxf(hi, 0.f));
}

// -------- kA: P1 = Wo@Wp, build w1dup/b1dup, zero stats --------
__global__ void kA(const float* __restrict__ Wo, const float* __restrict__ Wp,
                   const float* __restrict__ W1, const float* __restrict__ b1) {
    __shared__ float wp_s[H_DIM * 8];
    int t = threadIdx.x;
    int tid = blockIdx.x * 256 + t;
    for (int i = t; i < H_DIM * 8; i += 256) wp_s[i] = Wp[i];
    __syncthreads();
    int j = tid >> 3, k = tid & 7;
    const float* row = Wo + j * H_DIM;
    float acc = 0.f;
    #pragma unroll 8
    for (int q = 0; q < H_DIM; q++) acc = fmaf(row[q], wp_s[q * 8 + k], acc);
    g_P1[j * 8 + k] = acc;
    float wv = W1[k * H_DIM + j];          // W1 is [8,256] row-major; d=k
    g_w1dup[j * 8 + k] = pack2(wv, wv);
    if (tid < H_DIM) {
        float b = b1[tid];
        g_b1dup[tid] = pack2(b, b);
        g_sum[tid] = 0.f;
        g_sumsq[tid] = 0.f;
    }
}

// -------- kB: P2 = Wv@P1 --------
__global__ void kB(const float* __restrict__ Wv) {
    __shared__ float p1_s[H_DIM * 8];
    int t = threadIdx.x;
    int tid = blockIdx.x * 256 + t;
    for (int i = t; i < H_DIM * 8; i += 256) p1_s[i] = g_P1[i];
    __syncthreads();
    int j = tid >> 3, k = tid & 7;
    const float* row = Wv + j * H_DIM;
    float acc = 0.f;
    #pragma unroll 8
    for (int q = 0; q < H_DIM; q++) acc = fmaf(row[q], p1_s[q * 8 + k], acc);
    g_P2[j * 8 + k] = acc;
}

// -------- kC: Craw = W2@P2 (unscaled) --------
__global__ void kC(const float* __restrict__ W2) {
    __shared__ float p2_s[H_DIM * 8];
    int t = threadIdx.x;
    int tid = blockIdx.x * 256 + t;
    for (int i = t; i < H_DIM * 8; i += 256) p2_s[i] = g_P2[i];
    __syncthreads();
    int j = tid >> 3, k = tid & 7;
    const float* row = W2 + j * H_DIM;
    float acc = 0.f;
    #pragma unroll 8
    for (int q = 0; q < H_DIM; q++) acc = fmaf(row[q], p2_s[q * 8 + k], acc);
    g_Craw[j * 8 + k] = acc;
}

// -------- k1: gather nc, cache it packed, per-column relu stats --------
__global__ void __launch_bounds__(256) k1(const int* __restrict__ eidx,
                                          const float* __restrict__ nf) {
    __shared__ u64 ncs[256 * 8];
    int t = threadIdx.x;
    int base = blockIdx.x * 256;
    int cnt = min(256, PAIRS - base);
    const float4* nf4 = (const float4*)nf;

    if (t < cnt) {
        int p  = base + t;
        int e0 = 2 * p;
        int sA = eidx[e0],        sB = eidx[e0 + 1];
        int dA = eidx[E_NUM + e0], dB = eidx[E_NUM + e0 + 1];
        float4 sa0 = nf4[2 * sA], sa1 = nf4[2 * sA + 1];
        float4 da0 = nf4[2 * dA], da1 = nf4[2 * dA + 1];
        float4 sb0 = nf4[2 * sB], sb1 = nf4[2 * sB + 1];
        float4 db0 = nf4[2 * dB], db1 = nf4[2 * dB + 1];

        u64 ncp[8];
        ncp[0] = pack2(0.5f * (sa0.x + da0.x), 0.5f * (sb0.x + db0.x));
        ncp[1] = pack2(0.5f * (sa0.y + da0.y), 0.5f * (sb0.y + db0.y));
        ncp[2] = pack2(0.5f * (sa0.z + da0.z), 0.5f * (sb0.z + db0.z));
        ncp[3] = pack2(0.5f * (sa0.w + da0.w), 0.5f * (sb0.w + db0.w));
        ncp[4] = pack2(0.5f * (sa1.x + da1.x), 0.5f * (sb1.x + db1.x));
        ncp[5] = pack2(0.5f * (sa1.y + da1.y), 0.5f * (sb1.y + db1.y));
        ncp[6] = pack2(0.5f * (sa1.z + da1.z), 0.5f * (sb1.z + db1.z));
        ncp[7] = pack2(0.5f * (sa1.w + da1.w), 0.5f * (sb1.w + db1.w));

        #pragma unroll
        for (int d = 0; d < 8; d++) ncs[t * 8 + d] = ncp[d];
        ulonglong2* dst = (ulonglong2*)&g_nc2[(size_t)p * 8];
        dst[0] = make_ulonglong2(ncp[0], ncp[1]);
        dst[1] = make_ulonglong2(ncp[2], ncp[3]);
        dst[2] = make_ulonglong2(ncp[4], ncp[5]);
        dst[3] = make_ulonglong2(ncp[6], ncp[7]);
    }
    __syncthreads();

    int j = t;  // this thread owns hidden column j
    const ulonglong2* wd = (const ulonglong2*)&g_w1dup[j * 8];
    ulonglong2 w01 = wd[0], w23 = wd[1], w45 = wd[2], w67 = wd[3];
    u64 bdup = g_b1dup[j];
    u64 sum2 = 0ull, sq2 = 0ull;

    #pragma unroll 2
    for (int e2 = 0; e2 < cnt; e2++) {
        const ulonglong2* c = (const ulonglong2*)&ncs[e2 * 8];
        ulonglong2 c01 = c[0], c23 = c[1], c45 = c[2], c67 = c[3];
        u64 h = bdup;
        h = fma2(c01.x, w01.x, h); h = fma2(c01.y, w01.y, h);
        h = fma2(c23.x, w23.x, h); h = fma2(c23.y, w23.y, h);
        h = fma2(c45.x, w45.x, h); h = fma2(c45.y, w45.y, h);
        h = fma2(c67.x, w67.x, h); h = fma2(c67.y, w67.y, h);
        h = relu2(h);
        sum2 = add2(sum2, h);
        sq2  = fma2(h, h, sq2);
    }
    float slo, shi, qlo, qhi;
    unpack2(sum2, slo, shi);
    unpack2(sq2, qlo, qhi);
    atomicAdd(&g_sum[j],   slo + shi);
    atomicAdd(&g_sumsq[j], qlo + qhi);
}

// -------- kV (NEW): finalize stats + fold bias chain via precomputed [256,8] mats
// d = c@Craw + b2@P2 + bv@P1 + bo@Wp + bp  (four 256-length dots per output k)
// mdup[j,k] = 0.5 * a[j] * Craw[j,k]
__global__ void kV(const float* __restrict__ gamma, const float* __restrict__ beta,
                   const float* __restrict__ b2, const float* __restrict__ bv,
                   const float* __restrict__ bo, const float* __restrict__ Wp,
                   const float* __restrict__ bp) {
    __shared__ float a_s[H_DIM], c_s[H_DIM];
    int t = threadIdx.x;
    const float invE = 1.f / (float)E_NUM;
    float mu  = g_sum[t] * invE;
    float var = g_sumsq[t] * invE - mu * mu;
    float aj  = gamma[t] * rsqrtf(var + BN_EPS);
    a_s[t] = aj;
    c_s[t] = beta[t] - mu * aj;
    __syncthreads();

    // 8 warps, warp w owns output column k=w
    int w = t >> 5, lane = t & 31;
    float acc = 0.f;
    #pragma unroll
    for (int j0 = 0; j0 < H_DIM; j0 += 32) {
        int j = j0 + lane;
        acc += c_s[j] * g_Craw[j * 8 + w]
             + b2[j]  * g_P2[j * 8 + w]
             + bv[j]  * g_P1[j * 8 + w]
             + bo[j]  * Wp[j * 8 + w];
    }
    #pragma unroll
    for (int off = 16; off; off >>= 1)
        acc += __shfl_down_sync(0xffffffffu, acc, off);
    if (lane == 0) {
        float d = 0.5f * (acc + bp[w]);
        g_dhdup[w] = pack2(d, d);
    }

    // mdup: duplicated, 0.5*a-folded contraction matrix
    #pragma unroll
    for (int i = t; i < H_DIM * 8; i += 256) {
        int j = i >> 3;
        float m = 0.5f * a_s[j] * g_Craw[i];
        g_mdup[i] = pack2(m, m);
    }
}

// -------- k3: main pass, two edges per thread via f32x2 --------
__global__ void __launch_bounds__(256) k3(const float* __restrict__ ea,
                                          float* __restrict__ out) {
    __shared__ u64 w1s[H_DIM * 8];
    __shared__ u64 ms[H_DIM * 8];
    __shared__ u64 b1s[H_DIM];
    int t = threadIdx.x;
    {
        ulonglong2* wd = (ulonglong2*)w1s;
        ulonglong2* md = (ulonglong2*)ms;
        const ulonglong2* wsrc = (const ulonglong2*)g_w1dup;
        const ulonglong2* msrc = (const ulonglong2*)g_mdup;
        #pragma unroll
        for (int i = t; i < H_DIM * 4; i += 256) { wd[i] = wsrc[i]; md[i] = msrc[i]; }
        b1s[t] = g_b1dup[t];
    }
    __syncthreads();

    int p = blockIdx.x * 256 + t;
    if (p >= PAIRS) return;

    const ulonglong2* ncg = (const ulonglong2*)&g_nc2[(size_t)p * 8];
    ulonglong2 n01 = ncg[0], n23 = ncg[1], n45 = ncg[2], n67 = ncg[3];

    u64 acc0 = g_dhdup[0], acc1 = g_dhdup[1], acc2 = g_dhdup[2], acc3 = g_dhdup[3];
    u64 acc4 = g_dhdup[4], acc5 = g_dhdup[5], acc6 = g_dhdup[6], acc7 = g_dhdup[7];

    #pragma unroll 4
    for (int j = 0; j < H_DIM; j++) {
        const ulonglong2* w = (const ulonglong2*)&w1s[j * 8];
        ulonglong2 w01 = w[0], w23 = w[1], w45 = w[2], w67 = w[3];
        u64 h = b1s[j];
        h = fma2(n01.x, w01.x, h); h = fma2(n01.y, w01.y, h);
        h = fma2(n23.x, w23.x, h); h = fma2(n23.y, w23.y, h);
        h = fma2(n45.x, w45.x, h); h = fma2(n45.y, w45.y, h);
        h = fma2(n67.x, w67.x, h); h = fma2(n67.y, w67.y, h);
        h = relu2(h);
        const ulonglong2* m = (const ulonglong2*)&ms[j * 8];
        ulonglong2 m01 = m[0], m23 = m[1], m45 = m[2], m67 = m[3];
        acc0 = fma2(h, m01.x, acc0); acc1 = fma2(h, m01.y, acc1);
        acc2 = fma2(h, m23.x, acc2); acc3 = fma2(h, m23.y, acc3);
        acc4 = fma2(h, m45.x, acc4); acc5 = fma2(h, m45.y, acc5);
        acc6 = fma2(h, m67.x, acc6); acc7 = fma2(h, m67.y, acc7);
    }

    const float4* ea4 = (const float4*)ea;
    float4 eA0 = ea4[4 * p + 0], eA1 = ea4[4 * p + 1];
    float4 eB0 = ea4[4 * p + 2], eB1 = ea4[4 * p + 3];
    float lo, hi;
    float4 oA0, oA1, oB0, oB1;
    unpack2(acc0, lo, hi); oA0.x = eA0.x + lo; oB0.x = eB0.x + hi;
    unpack2(acc1, lo, hi); oA0.y = eA0.y + lo; oB0.y = eB0.y + hi;
    unpack2(acc2, lo, hi); oA0.z = eA0.z + lo; oB0.z = eB0.z + hi;
    unpack2(acc3, lo, hi); oA0.w = eA0.w + lo; oB0.w = eB0.w + hi;
    unpack2(acc4, lo, hi); oA1.x = eA1.x + lo; oB1.x = eB1.x + hi;
    unpack2(acc5, lo, hi); oA1.y = eA1.y + lo; oB1.y = eB1.y + hi;
    unpack2(acc6, lo, hi); oA1.z = eA1.z + lo; oB1.z = eB1.z + hi;
    unpack2(acc7, lo, hi); oA1.w = eA1.w + lo; oB1.w = eB1.w + hi;

    float4* out4 = (float4*)out;
    out4[4 * p + 0] = oA0;
    out4[4 * p + 1] = oA1;
    out4[4 * p + 2] = oB0;
    out4[4 * p + 3] = oB1;
}

// -------- launch --------
extern "C" void kernel_launch(void* const* d_in, const int* in_sizes, int n_in,
                              void* d_out, int out_size) {
    (void)in_sizes; (void)n_in; (void)out_size;
    const float* edge_attr = (const float*)d_in[0];
    const float* nf        = (const float*)d_in[1];
    const int*   eidx      = (const int*)d_in[2];
    // d_in[3..8] = edge-encoder weights: provably dead code in the reference
    const float* W1    = (const float*)d_in[9];
    const float* b1    = (const float*)d_in[10];
    const float* gamma = (const float*)d_in[11];
    const float* beta  = (const float*)d_in[12];
    const float* W2    = (const float*)d_in[13];
    const float* b2    = (const float*)d_in[14];
    const float* Wv    = (const float*)d_in[15];
    const float* bv    = (const float*)d_in[16];
    const float* Wo    = (const float*)d_in[17];
    const float* bo    = (const float*)d_in[18];
    const float* Wp    = (const float*)d_in[19];
    const float* bp    = (const float*)d_in[20];
    float* out = (float*)d_out;

    kA<<<8, 256>>>(Wo, Wp, W1, b1);      // P1, w1dup, b1dup, zero stats
    k1<<<NBLK1, 256>>>(eidx, nf);        // gather + cache nc + relu stats
    kB<<<8, 256>>>(Wv);                  // P2
    kC<<<8, 256>>>(W2);                  // Craw
    kV<<<1, 256>>>(gamma, beta, b2, bv, bo, Wp, bp);  // a, c, d, mdup (tiny now)
    k3<<<NBLK1, 256>>>(edge_attr, out);  // main contraction + epilogue
}

// round 3
// speedup vs baseline: 2.0643x; 2.0643x over previous
#include <cuda_runtime.h>
#include <cstdint>

#define E_NUM   500000
#define H_DIM   256
#define PAIRS   (E_NUM / 2)      // 250000
#define BN_EPS  1e-5f
#define GRID    296              // 148 SMs x 2 co-resident blocks
#define PER1    848              // pairs/block, blocks 1..295 (phase 1)
#define PER2    845              // pairs/block, blocks 0..295 (phase 2)

typedef unsigned long long u64;

// -------- device scratch (static, no allocation) --------
__device__ float g_sum[H_DIM];                     // zero-init
__device__ float g_sumsq[H_DIM];
__device__ __align__(16) u64 g_nc2[PAIRS * 8];     // packed nc pairs, 16 MB
__device__ float g_Craw[H_DIM * 8];                // W2@Wv@Wo@Wp
__device__ float g_biaspart[8];                    // b2@P2 + bv@P1 + bo@Wp + bp
__device__ unsigned g_arrive = 0;
__device__ volatile unsigned g_release = 0;
__device__ unsigned g_finish = 0;

// -------- f32x2 helpers --------
__device__ __forceinline__ u64 pack2(float lo, float hi) {
    u64 r;
    asm("mov.b64 %0, {%1, %2};" : "=l"(r)
        : "r"(__float_as_uint(lo)), "r"(__float_as_uint(hi)));
    return r;
}
__device__ __forceinline__ void unpack2(u64 v, float &lo, float &hi) {
    unsigned int a, b;
    asm("mov.b64 {%0, %1}, %2;" : "=r"(a), "=r"(b) : "l"(v));
    lo = __uint_as_float(a); hi = __uint_as_float(b);
}
__device__ __forceinline__ u64 fma2(u64 a, u64 b, u64 c) {
    u64 d;
    asm("fma.rn.f32x2 %0, %1, %2, %3;" : "=l"(d) : "l"(a), "l"(b), "l"(c));
    return d;
}
__device__ __forceinline__ u64 add2(u64 a, u64 b) {
    u64 d;
    asm("add.rn.f32x2 %0, %1, %2;" : "=l"(d) : "l"(a), "l"(b));
    return d;
}
__device__ __forceinline__ u64 relu2(u64 h) {
    float lo, hi; unpack2(h, lo, hi);
    return pack2(fmaxf(lo, 0.f), fmaxf(hi, 0.f));
}
__device__ __forceinline__ float wred(float v) {
    v += __shfl_down_sync(0xffffffffu, v, 16);
    v += __shfl_down_sync(0xffffffffu, v, 8);
    v += __shfl_down_sync(0xffffffffu, v, 4);
    v += __shfl_down_sync(0xffffffffu, v, 2);
    v += __shfl_down_sync(0xffffffffu, v, 1);
    return v;
}

__global__ void __launch_bounds__(256, 2)
fused(const float* __restrict__ ea, const float* __restrict__ nf,
      const int*   __restrict__ eidx,
      const float* __restrict__ W1, const float* __restrict__ b1,
      const float* __restrict__ gamma, const float* __restrict__ beta,
      const float* __restrict__ W2, const float* __restrict__ b2,
      const float* __restrict__ Wv, const float* __restrict__ bv,
      const float* __restrict__ Wo, const float* __restrict__ bo,
      const float* __restrict__ Wp, const float* __restrict__ bp,
      float* __restrict__ out)
{
    // s_buf aliases: phase1 ncs (u64[2048], 16KB) / block0 chain (2x2304 floats,
    // padded rows of 9) / phase2 ms (u64[2048], 16KB)
    __shared__ __align__(16) unsigned char s_buf[18432];
    __shared__ __align__(16) u64 w1s[H_DIM * 8];   // W1^T duplicated
    __shared__ u64 b1s[H_DIM];
    __shared__ u64 dh_s[8];
    __shared__ float a_s[H_DIM], c_s[H_DIM];

    const int t = threadIdx.x;
    const int b = blockIdx.x;
    const int lane = t & 31, warp = t >> 5;

    // ---- build duplicated W1^T / b1 tables (own-thread writes, no sync needed yet)
    #pragma unroll
    for (int d = 0; d < 8; d++) {
        float v = W1[d * H_DIM + t];
        w1s[t * 8 + d] = pack2(v, v);
    }
    { float bb = b1[t]; b1s[t] = pack2(bb, bb); }

    if (b == 0) {
        // ================= weight chain (runs under the stats pass) ==========
        float* bufA = (float*)s_buf;      // 2304 floats (256 rows x 9, padded)
        float* bufB = bufA + 2304;
        // load Wp padded
        for (int i = t; i < H_DIM * 8; i += 256)
            bufA[(i >> 3) * 9 + (i & 7)] = Wp[i];
        __syncthreads();
        // bias: bo @ Wp  (warp w owns output k=w; conflict-free, 9 coprime 32)
        float biask = 0.f;
        for (int j = lane; j < H_DIM; j += 32) biask += bo[j] * bufA[j * 9 + warp];
        // stage 1: P1 = Wo @ Wp   (bufA -> bufB), warp-per-row, coalesced LDG
        for (int jj = warp; jj < H_DIM; jj += 8) {
            float a0=0,a1=0,a2=0,a3=0,a4=0,a5=0,a6=0,a7=0;
            #pragma unroll
            for (int qb = 0; qb < 8; qb++) {
                int q = qb * 32 + lane;
                float av = Wo[jj * H_DIM + q];
                const float* ir = bufA + q * 9;
                a0 += av*ir[0]; a1 += av*ir[1]; a2 += av*ir[2]; a3 += av*ir[3];
                a4 += av*ir[4]; a5 += av*ir[5]; a6 += av*ir[6]; a7 += av*ir[7];
            }
            a0=wred(a0); a1=wred(a1); a2=wred(a2); a3=wred(a3);
            a4=wred(a4); a5=wred(a5); a6=wred(a6); a7=wred(a7);
            if (lane == 0) {
                float* orow = bufB + jj * 9;
                orow[0]=a0; orow[1]=a1; orow[2]=a2; orow[3]=a3;
                orow[4]=a4; orow[5]=a5; orow[6]=a6; orow[7]=a7;
            }
        }
        __syncthreads();
        // bias: bv @ P1
        for (int j = lane; j < H_DIM; j += 32) biask += bv[j] * bufB[j * 9 + warp];
        // stage 2: P2 = Wv @ P1   (bufB -> bufA; Wp no longer needed)
        for (int jj = warp; jj < H_DIM; jj += 8) {
            float a0=0,a1=0,a2=0,a3=0,a4=0,a5=0,a6=0,a7=0;
            #pragma unroll
            for (int qb = 0; qb < 8; qb++) {
                int q = qb * 32 + lane;
                float av = Wv[jj * H_DIM + q];
                const float* ir = bufB + q * 9;
                a0 += av*ir[0]; a1 += av*ir[1]; a2 += av*ir[2]; a3 += av*ir[3];
                a4 += av*ir[4]; a5 += av*ir[5]; a6 += av*ir[6]; a7 += av*ir[7];
            }
            a0=wred(a0); a1=wred(a1); a2=wred(a2); a3=wred(a3);
            a4=wred(a4); a5=wred(a5); a6=wred(a6); a7=wred(a7);
            if (lane == 0) {
                float* orow = bufA + jj * 9;
                orow[0]=a0; orow[1]=a1; orow[2]=a2; orow[3]=a3;
                orow[4]=a4; orow[5]=a5; orow[6]=a6; orow[7]=a7;
            }
        }
        __syncthreads();
        // bias: b2 @ P2
        for (int j = lane; j < H_DIM; j += 32) biask += b2[j] * bufA[j * 9 + warp];
        // stage 3: Craw = W2 @ P2 -> global
        for (int jj = warp; jj < H_DIM; jj += 8) {
            float a0=0,a1=0,a2=0,a3=0,a4=0,a5=0,a6=0,a7=0;
            #pragma unroll
            for (int qb = 0; qb < 8; qb++) {
                int q = qb * 32 + lane;
                float av = W2[jj * H_DIM + q];
                const float* ir = bufA + q * 9;
                a0 += av*ir[0]; a1 += av*ir[1]; a2 += av*ir[2]; a3 += av*ir[3];
                a4 += av*ir[4]; a5 += av*ir[5]; a6 += av*ir[6]; a7 += av*ir[7];
            }
            a0=wred(a0); a1=wred(a1); a2=wred(a2); a3=wred(a3);
            a4=wred(a4); a5=wred(a5); a6=wred(a6); a7=wred(a7);
            if (lane == 0) {
                float* orow = g_Craw + jj * 8;
                orow[0]=a0; orow[1]=a1; orow[2]=a2; orow[3]=a3;
                orow[4]=a4; orow[5]=a5; orow[6]=a6; orow[7]=a7;
            }
        }
        biask = wred(biask);   // harmless: only lane0's value used
        if (lane == 0) g_biaspart[warp] = biask + bp[warp];
        // (biask accumulated per-lane partials; wred sums across lanes)
    } else {
        // ================= phase 1: gather + cache nc + relu stats ===========
        int s1 = (b - 1) * PER1;
        int e1 = s1 + PER1; if (e1 > PAIRS) e1 = PAIRS;
        u64* ncs = (u64*)s_buf;
        const float4* nf4 = (const float4*)nf;

        const ulonglong2* wd = (const ulonglong2*)&w1s[t * 8];
        ulonglong2 w01 = wd[0], w23 = wd[1], w45 = wd[2], w67 = wd[3];
        u64 bdup = b1s[t];
        u64 sum2 = 0ull, sq2 = 0ull;

        for (int base = s1; base < e1; base += 256) {
            int cnt = e1 - base; if (cnt > 256) cnt = 256;
            __syncthreads();   // protect ncs reuse across tiles
            if (t < cnt) {
                int p  = base + t;
                int e0 = 2 * p;
                int sA = eidx[e0],         sB = eidx[e0 + 1];
                int dA = eidx[E_NUM + e0], dB = eidx[E_NUM + e0 + 1];
                float4 sa0 = nf4[2*sA], sa1 = nf4[2*sA+1];
                float4 da0 = nf4[2*dA], da1 = nf4[2*dA+1];
                float4 sb0 = nf4[2*sB], sb1 = nf4[2*sB+1];
                float4 db0 = nf4[2*dB], db1 = nf4[2*dB+1];
                u64 ncp[8];
                ncp[0] = pack2(0.5f*(sa0.x+da0.x), 0.5f*(sb0.x+db0.x));
                ncp[1] = pack2(0.5f*(sa0.y+da0.y), 0.5f*(sb0.y+db0.y));
                ncp[2] = pack2(0.5f*(sa0.z+da0.z), 0.5f*(sb0.z+db0.z));
                ncp[3] = pack2(0.5f*(sa0.w+da0.w), 0.5f*(sb0.w+db0.w));
                ncp[4] = pack2(0.5f*(sa1.x+da1.x), 0.5f*(sb1.x+db1.x));
                ncp[5] = pack2(0.5f*(sa1.y+da1.y), 0.5f*(sb1.y+db1.y));
                ncp[6] = pack2(0.5f*(sa1.z+da1.z), 0.5f*(sb1.z+db1.z));
                ncp[7] = pack2(0.5f*(sa1.w+da1.w), 0.5f*(sb1.w+db1.w));
                #pragma unroll
                for (int d = 0; d < 8; d++) ncs[t * 8 + d] = ncp[d];
                ulonglong2* dst = (ulonglong2*)&g_nc2[(size_t)p * 8];
                dst[0] = make_ulonglong2(ncp[0], ncp[1]);
                dst[1] = make_ulonglong2(ncp[2], ncp[3]);
                dst[2] = make_ulonglong2(ncp[4], ncp[5]);
                dst[3] = make_ulonglong2(ncp[6], ncp[7]);
            }
            __syncthreads();
            for (int e2 = 0; e2 < cnt; e2++) {
                const ulonglong2* c = (const ulonglong2*)&ncs[e2 * 8];
                ulonglong2 c01 = c[0], c23 = c[1], c45 = c[2], c67 = c[3];
                u64 h = bdup;
                h = fma2(c01.x, w01.x, h); h = fma2(c01.y, w01.y, h);
                h = fma2(c23.x, w23.x, h); h = fma2(c23.y, w23.y, h);
                h = fma2(c45.x, w45.x, h); h = fma2(c45.y, w45.y, h);
                h = fma2(c67.x, w67.x, h); h = fma2(c67.y, w67.y, h);
                h = relu2(h);
                sum2 = add2(sum2, h);
                sq2  = fma2(h, h, sq2);
            }
        }
        float slo, shi, qlo, qhi;
        unpack2(sum2, slo, shi);
        unpack2(sq2, qlo, qhi);
        atomicAdd(&g_sum[t],   slo + shi);
        atomicAdd(&g_sumsq[t], qlo + qhi);
    }

    // ================= grid barrier =================
    __syncthreads();
    if (t == 0) {
        __threadfence();
        if (atomicAdd(&g_arrive, 1) == GRID - 1) {
            g_release = 1;
        } else {
            while (g_release == 0) { }
        }
        __threadfence();
    }
    __syncthreads();

    // ================= phase 1.5: finalize BN, dh, ms (per block) ===========
    {
        const float invE = 1.f / (float)E_NUM;
        float mu  = g_sum[t] * invE;
        float var = g_sumsq[t] * invE - mu * mu;
        float aj  = gamma[t] * rsqrtf(var + BN_EPS);
        a_s[t] = aj;
        c_s[t] = beta[t] - mu * aj;
    }
    __syncthreads();
    {   // dh[k] = 0.5*(c@Craw[:,k] + biaspart[k]); warp w owns k=w
        float acc = 0.f;
        for (int j = lane; j < H_DIM; j += 32) acc += c_s[j] * g_Craw[j * 8 + warp];
        acc = wred(acc);
        if (lane == 0) {
            float d = 0.5f * (acc + g_biaspart[warp]);
            dh_s[warp] = pack2(d, d);
        }
    }
    u64* ms = (u64*)s_buf;
    __syncthreads();
    for (int i = t; i < H_DIM * 8; i += 256) {
        float m = 0.5f * a_s[i >> 3] * g_Craw[i];
        ms[i] = pack2(m, m);
    }
    __syncthreads();

    // ================= phase 2: main contraction, 2 pairs/thread ============
    int s2 = b * PER2;
    int e2p = s2 + PER2; if (e2p > PAIRS) e2p = PAIRS;
    const float4* ea4 = (const float4*)ea;
    float4* out4 = (float4*)out;

    for (int base = s2; base < e2p; base += 512) {
        int pA = base + t;
        int pB = base + 256 + t;
        bool vA = pA < e2p, vB = pB < e2p;

        ulonglong2 nA0, nA1, nA2, nA3, nB0, nB1, nB2, nB3;
        if (vA) {
            const ulonglong2* g = (const ulonglong2*)&g_nc2[(size_t)pA * 8];
            nA0 = g[0]; nA1 = g[1]; nA2 = g[2]; nA3 = g[3];
        } else {
            nA0 = nA1 = nA2 = nA3 = make_ulonglong2(0ull, 0ull);
        }
        if (vB) {
            const ulonglong2* g = (const ulonglong2*)&g_nc2[(size_t)pB * 8];
            nB0 = g[0]; nB1 = g[1]; nB2 = g[2]; nB3 = g[3];
        } else {
            nB0 = nB1 = nB2 = nB3 = make_ulonglong2(0ull, 0ull);
        }

        u64 aA0 = dh_s[0], aA1 = dh_s[1], aA2 = dh_s[2], aA3 = dh_s[3];
        u64 aA4 = dh_s[4], aA5 = dh_s[5], aA6 = dh_s[6], aA7 = dh_s[7];
        u64 aB0 = aA0, aB1 = aA1, aB2 = aA2, aB3 = aA3;
        u64 aB4 = aA4, aB5 = aA5, aB6 = aA6, aB7 = aA7;

        #pragma unroll 2
        for (int j = 0; j < H_DIM; j++) {
            const ulonglong2* w = (const ulonglong2*)&w1s[j * 8];
            ulonglong2 w01 = w[0], w23 = w[1], w45 = w[2], w67 = w[3];
            u64 bb = b1s[j];
            u64 hA = bb;
            hA = fma2(nA0.x, w01.x, hA); hA = fma2(nA0.y, w01.y, hA);
            hA = fma2(nA1.x, w23.x, hA); hA = fma2(nA1.y, w23.y, hA);
            hA = fma2(nA2.x, w45.x, hA); hA = fma2(nA2.y, w45.y, hA);
            hA = fma2(nA3.x, w67.x, hA); hA = fma2(nA3.y, w67.y, hA);
            hA = relu2(hA);
            u64 hB = bb;
            hB = fma2(nB0.x, w01.x, hB); hB = fma2(nB0.y, w01.y, hB);
            hB = fma2(nB1.x, w23.x, hB); hB = fma2(nB1.y, w23.y, hB);
            hB = fma2(nB2.x, w45.x, hB); hB = fma2(nB2.y, w45.y, hB);
            hB = fma2(nB3.x, w67.x, hB); hB = fma2(nB3.y, w67.y, hB);
            hB = relu2(hB);
            const ulonglong2* m = (const ulonglong2*)&ms[j * 8];
            ulonglong2 m01 = m[0], m23 = m[1], m45 = m[2], m67 = m[3];
            aA0 = fma2(hA, m01.x, aA0); aA1 = fma2(hA, m01.y, aA1);
            aA2 = fma2(hA, m23.x, aA2); aA3 = fma2(hA, m23.y, aA3);
            aA4 = fma2(hA, m45.x, aA4); aA5 = fma2(hA, m45.y, aA5);
            aA6 = fma2(hA, m67.x, aA6); aA7 = fma2(hA, m67.y, aA7);
            aB0 = fma2(hB, m01.x, aB0); aB1 = fma2(hB, m01.y, aB1);
            aB2 = fma2(hB, m23.x, aB2); aB3 = fma2(hB, m23.y, aB3);
            aB4 = fma2(hB, m45.x, aB4); aB5 = fma2(hB, m45.y, aB5);
            aB6 = fma2(hB, m67.x, aB6); aB7 = fma2(hB, m67.y, aB7);
        }

        if (vA) {
            float4 e0 = ea4[4*pA+0], e1 = ea4[4*pA+1], e2 = ea4[4*pA+2], e3 = ea4[4*pA+3];
            float lo, hi; float4 o0, o1, o2, o3;
            unpack2(aA0, lo, hi); o0.x = e0.x + lo; o2.x = e2.x + hi;
            unpack2(aA1, lo, hi); o0.y = e0.y + lo; o2.y = e2.y + hi;
            unpack2(aA2, lo, hi); o0.z = e0.z + lo; o2.z = e2.z + hi;
            unpack2(aA3, lo, hi); o0.w = e0.w + lo; o2.w = e2.w + hi;
            unpack2(aA4, lo, hi); o1.x = e1.x + lo; o3.x = e3.x + hi;
            unpack2(aA5, lo, hi); o1.y = e1.y + lo; o3.y = e3.y + hi;
            unpack2(aA6, lo, hi); o1.z = e1.z + lo; o3.z = e3.z + hi;
            unpack2(aA7, lo, hi); o1.w = e1.w + lo; o3.w = e3.w + hi;
            out4[4*pA+0] = o0; out4[4*pA+1] = o1; out4[4*pA+2] = o2; out4[4*pA+3] = o3;
        }
        if (vB) {
            float4 e0 = ea4[4*pB+0], e1 = ea4[4*pB+1], e2 = ea4[4*pB+2], e3 = ea4[4*pB+3];
            float lo, hi; float4 o0, o1, o2, o3;
            unpack2(aB0, lo, hi); o0.x = e0.x + lo; o2.x = e2.x + hi;
            unpack2(aB1, lo, hi); o0.y = e0.y + lo; o2.y = e2.y + hi;
            unpack2(aB2, lo, hi); o0.z = e0.z + lo; o2.z = e2.z + hi;
            unpack2(aB3, lo, hi); o0.w = e0.w + lo; o2.w = e2.w + hi;
            unpack2(aB4, lo, hi); o1.x = e1.x + lo; o3.x = e3.x + hi;
            unpack2(aB5, lo, hi); o1.y = e1.y + lo; o3.y = e3.y + hi;
            unpack2(aB6, lo, hi); o1.z = e1.z + lo; o3.z = e3.z + hi;
            unpack2(aB7, lo, hi); o1.w = e1.w + lo; o3.w = e3.w + hi;
            out4[4*pB+0] = o0; out4[4*pB+1] = o1; out4[4*pB+2] = o2; out4[4*pB+3] = o3;
        }
    }

    // ================= reset (last finisher) =================
    __syncthreads();
    if (t == 0) {
        __threadfence();
        if (atomicAdd(&g_finish, 1) == GRID - 1) {
            g_arrive = 0;
            g_release = 0;
            for (int i = 0; i < H_DIM; i++) { g_sum[i] = 0.f; g_sumsq[i] = 0.f; }
            __threadfence();
            g_finish = 0;
        }
    }
}

// -------- launch --------
extern "C" void kernel_launch(void* const* d_in, const int* in_sizes, int n_in,
                              void* d_out, int out_size) {
    (void)in_sizes; (void)n_in; (void)out_size;
    const float* edge_attr = (const float*)d_in[0];
    const float* nf        = (const float*)d_in[1];
    const int*   eidx      = (const int*)d_in[2];
    // d_in[3..8] = edge-encoder weights: dead code in the reference
    const float* W1    = (const float*)d_in[9];
    const float* b1    = (const float*)d_in[10];
    const float* gamma = (const float*)d_in[11];
    const float* beta  = (const float*)d_in[12];
    const float* W2    = (const float*)d_in[13];
    const float* b2    = (const float*)d_in[14];
    const float* Wv    = (const float*)d_in[15];
    const float* bv    = (const float*)d_in[16];
    const float* Wo    = (const float*)d_in[17];
    const float* bo    = (const float*)d_in[18];
    const float* Wp    = (const float*)d_in[19];
    const float* bp    = (const float*)d_in[20];
    float* out = (float*)d_out;

    fused<<<GRID, 256>>>(edge_attr, nf, eidx, W1, b1, gamma, beta,
                         W2, b2, Wv, bv, Wo, bo, Wp, bp, out);
}